// round 2
// baseline (speedup 1.0000x reference)
#include <cuda_runtime.h>
#include <float.h>
#include <math.h>

#define C_ 32
#define D_ 48
#define H_ 64
#define W_ 128
#define HW 8192          // H_*W_
#define CDHW 12582912    // C_*D_*H_*W_
#define GDIR 1310720     // C_*5*HW
#define FULLMASK 0xffffffffu

// Scratch (allocation-free rule: __device__ globals)
__device__ float g_agg[CDHW];
__device__ float g_y[CDHW];

__device__ __forceinline__ float wmax48(float m) {
#pragma unroll
    for (int o = 16; o; o >>= 1) m = fmaxf(m, __shfl_xor_sync(FULLMASK, m, o));
    return m;
}

// One SGA recurrence step. Lane L holds d0=2L, d1=2L+1 (L<24 active).
__device__ __forceinline__ void sga_step(bool first, bool act, int L,
    float xe0, float xe1,
    float w0, float w1, float w2, float w3, float w4,
    float& a0, float& a1)
{
    if (first) {
        a0 = act ? xe0 : -FLT_MAX;
        a1 = act ? xe1 : -FLT_MAX;
    } else {
        float s = fabsf(w0) + fabsf(w1) + fabsf(w2) + fabsf(w3) + fabsf(w4);
        float inv = __fdividef(1.0f, fmaxf(s, 1e-12f));
        float up = __shfl_up_sync(FULLMASK, a1, 1);    // prev[d0-1]
        float dn = __shfl_down_sync(FULLMASK, a0, 1);  // prev[d1+1]
        if (L == 0)  up = 0.0f;
        if (L == 23) dn = 0.0f;
        float m = act ? fmaxf(a0, a1) : -FLT_MAX;
        m = wmax48(m);
        float n0 = w0 * xe0 + w1 * a0 + w2 * up + w3 * a1 + w4 * m;
        float n1 = w0 * xe1 + w1 * a1 + w2 * a0 + w3 * dn + w4 * m;
        a0 = n0 * inv;
        a1 = n1 * inv;
    }
}

// ---------------- W-direction scans (DIR 0 = fwd/store, DIR 1 = rev/max) ----
template<int DIR, int MODE>
__global__ void __launch_bounds__(128) sga_w(const float* __restrict__ x,
                                             const float* __restrict__ g)
{
    const int warp = blockIdx.x * 4 + (threadIdx.x >> 5);   // 0..2047 = c*64+h
    const int L = threadIdx.x & 31;
    const bool act = L < 24;
    const int c = warp >> 6;
    const int h = warp & 63;
    const int dd = act ? (2 * L) : 0;
    const size_t b0 = ((size_t)(c * D_ + dd) * H_ + h) * (size_t)W_;
    const float4* xr0 = (const float4*)(x + b0);
    const float4* xr1 = (const float4*)(x + b0 + (act ? HW : 0));
    float4* ar0 = (float4*)(g_agg + b0);
    float4* ar1 = (float4*)(g_agg + b0 + (act ? HW : 0));
    const float* kb = g + (size_t)DIR * GDIR + (size_t)(c * 5) * HW + h * W_;

    float a0 = -FLT_MAX, a1 = -FLT_MAX;
    const bool rev = (DIR == 1);

    for (int gi = 0; gi < 32; ++gi) {
        const int grp = rev ? (31 - gi) : gi;
        float4 xv0 = xr0[grp];
        float4 xv1 = xr1[grp];
        float4 kv0 = ((const float4*)(kb          ))[grp];
        float4 kv1 = ((const float4*)(kb +     HW ))[grp];
        float4 kv2 = ((const float4*)(kb + 2 * HW ))[grp];
        float4 kv3 = ((const float4*)(kb + 3 * HW ))[grp];
        float4 kv4 = ((const float4*)(kb + 4 * HW ))[grp];
        float o0[4], o1[4];
#pragma unroll
        for (int jj = 0; jj < 4; ++jj) {
            const int j = rev ? (3 - jj) : jj;
            const bool first = (gi == 0) && (jj == 0);
            sga_step(first, act, L,
                     ((const float*)&xv0)[j], ((const float*)&xv1)[j],
                     ((const float*)&kv0)[j], ((const float*)&kv1)[j],
                     ((const float*)&kv2)[j], ((const float*)&kv3)[j],
                     ((const float*)&kv4)[j], a0, a1);
            o0[j] = a0; o1[j] = a1;
        }
        if (act) {
            float4 v0 = make_float4(o0[0], o0[1], o0[2], o0[3]);
            float4 v1 = make_float4(o1[0], o1[1], o1[2], o1[3]);
            if (MODE == 1) {
                float4 p0 = ar0[grp], p1 = ar1[grp];
                v0.x = fmaxf(v0.x, p0.x); v0.y = fmaxf(v0.y, p0.y);
                v0.z = fmaxf(v0.z, p0.z); v0.w = fmaxf(v0.w, p0.w);
                v1.x = fmaxf(v1.x, p1.x); v1.y = fmaxf(v1.y, p1.y);
                v1.z = fmaxf(v1.z, p1.z); v1.w = fmaxf(v1.w, p1.w);
            }
            ar0[grp] = v0;
            ar1[grp] = v1;
        }
    }
}

// ---------------- H-direction scans (DIR 2 = fwd/max, DIR 3 = rev/final) ---
// Block = 8 warps covering 8 adjacent w (L1 sector sharing of scalar loads).
template<int DIR, int MODE>
__global__ void __launch_bounds__(256) sga_h(const float* __restrict__ x,
                                             const float* __restrict__ g,
                                             const float* __restrict__ s1,
                                             const float* __restrict__ b1)
{
    const int c = blockIdx.x >> 4;
    const int w = ((blockIdx.x & 15) << 3) + (threadIdx.x >> 5);
    const int L = threadIdx.x & 31;
    const bool act = L < 24;
    const int dd = act ? (2 * L) : 0;
    const size_t b0 = ((size_t)(c * D_ + dd) * H_) * (size_t)W_ + w;
    const float* xr0 = x + b0;
    const float* xr1 = x + b0 + (act ? HW : 0);
    float* ar0 = g_agg + b0;
    float* ar1 = g_agg + b0 + (act ? HW : 0);
    float* yr0 = g_y + b0;
    float* yr1 = g_y + b0 + (act ? HW : 0);
    const float* kb = g + (size_t)DIR * GDIR + (size_t)(c * 5) * HW + w;

    float inv1 = 0.0f, bb1 = 0.0f;
    if (MODE == 2) {
        inv1 = s1[c] * rsqrtf(1.0f + 1e-5f);
        bb1 = b1[c];
    }

    float a0 = -FLT_MAX, a1 = -FLT_MAX;
    const bool rev = (DIR == 3);

    for (int hi = 0; hi < H_; ++hi) {
        const int hh = rev ? (H_ - 1 - hi) : hi;
        const int off = hh * W_;
        float xe0 = act ? __ldg(xr0 + off) : 0.0f;
        float xe1 = act ? __ldg(xr1 + off) : 0.0f;
        float w0 = __ldg(kb + off);
        float w1 = __ldg(kb + HW + off);
        float w2 = __ldg(kb + 2 * HW + off);
        float w3 = __ldg(kb + 3 * HW + off);
        float w4 = __ldg(kb + 4 * HW + off);
        sga_step(hi == 0, act, L, xe0, xe1, w0, w1, w2, w3, w4, a0, a1);
        if (act) {
            if (MODE == 1) {
                ar0[off] = fmaxf(ar0[off], a0);
                ar1[off] = fmaxf(ar1[off], a1);
            } else {
                float v0 = fmaxf(ar0[off], a0);
                float v1 = fmaxf(ar1[off], a1);
                yr0[off] = fmaxf(v0 * inv1 + bb1, 0.0f);
                yr1[off] = fmaxf(v1 * inv1 + bb1, 0.0f);
            }
        }
    }
}

// ---------------- 3x3x3 conv (32->32) + BN2 + residual + ReLU --------------
// One block per (d,h). 128 threads: thread = (cg 0..7)*16 + (wg 0..15),
// computes co = 4*cg..4*cg+3, w = 8*wg..8*wg+7 (32 accumulators).
__global__ void __launch_bounds__(128) conv_kernel(const float* __restrict__ wr,
                                                   const float* __restrict__ x,
                                                   const float* __restrict__ s2,
                                                   const float* __restrict__ b2,
                                                   float* __restrict__ out)
{
    __shared__ float insh[C_][136];      // padded input rows: idx = w+1, [0..129] valid
    __shared__ float wsh[C_ * 96];       // [ci][co*3+kw]

    const int d = blockIdx.x >> 6;
    const int h = blockIdx.x & 63;
    const int t = threadIdx.x;
    const int cg = t >> 4;               // 0..7
    const int wg = t & 15;               // 0..15

    float acc[4][8];
#pragma unroll
    for (int a = 0; a < 4; ++a)
#pragma unroll
        for (int b = 0; b < 8; ++b) acc[a][b] = 0.0f;

#pragma unroll
    for (int kd = 0; kd < 3; ++kd) {
        const int zd = d + kd - 1;
#pragma unroll
        for (int kh = 0; kh < 3; ++kh) {
            const int zh = h + kh - 1;
            const bool inb = (zd >= 0) && (zd < D_) && (zh >= 0) && (zh < H_);
            __syncthreads();
            if (inb) {
                // stage input rows (32 x 136, zero-padded ends)
                for (int j = t; j < C_ * 136; j += 128) {
                    const int ci = j / 136;
                    const int idx = j - ci * 136;
                    const int wi = idx - 1;
                    float v = 0.0f;
                    if (wi >= 0 && wi < W_)
                        v = g_y[((size_t)(ci * D_ + zd) * H_ + zh) * W_ + wi];
                    insh[ci][idx] = v;
                }
                // stage weight slice for this (kd,kh): wsh[ci*96 + co*3 + kw]
                for (int j = t; j < C_ * 96; j += 128) {
                    const int ci = j / 96;
                    const int r = j - ci * 96;
                    const int co = r / 3;
                    const int kw = r - co * 3;
                    wsh[j] = wr[(size_t)(co * C_ + ci) * 27 + kd * 9 + kh * 3 + kw];
                }
            }
            __syncthreads();
            if (!inb) continue;

#pragma unroll 2
            for (int ci = 0; ci < C_; ++ci) {
                const float* ip = &insh[ci][wg * 8];
                float4 iv0 = *(const float4*)(ip);
                float4 iv1 = *(const float4*)(ip + 4);
                float4 iv2 = *(const float4*)(ip + 8);
                float iv[12] = {iv0.x, iv0.y, iv0.z, iv0.w,
                                iv1.x, iv1.y, iv1.z, iv1.w,
                                iv2.x, iv2.y, iv2.z, iv2.w};
                const float* wp = &wsh[ci * 96 + cg * 12];
                float4 wv0 = *(const float4*)(wp);
                float4 wv1 = *(const float4*)(wp + 4);
                float4 wv2 = *(const float4*)(wp + 8);
                float wv[12] = {wv0.x, wv0.y, wv0.z, wv0.w,
                                wv1.x, wv1.y, wv1.z, wv1.w,
                                wv2.x, wv2.y, wv2.z, wv2.w};
#pragma unroll
                for (int co = 0; co < 4; ++co) {
#pragma unroll
                    for (int ww = 0; ww < 8; ++ww) {
                        acc[co][ww] = fmaf(iv[ww],     wv[co * 3],
                                     fmaf(iv[ww + 1], wv[co * 3 + 1],
                                     fmaf(iv[ww + 2], wv[co * 3 + 2], acc[co][ww])));
                    }
                }
            }
        }
    }

    // epilogue: BN2 + residual + ReLU
#pragma unroll
    for (int co = 0; co < 4; ++co) {
        const int oc = cg * 4 + co;
        const float inv = s2[oc] * rsqrtf(1.0f + 1e-5f);
        const float bb = b2[oc];
        const size_t off = ((size_t)(oc * D_ + d) * H_ + h) * W_ + wg * 8;
#pragma unroll
        for (int ww = 0; ww < 8; ++ww) {
            float v = acc[co][ww] * inv + bb + x[off + ww];
            out[off + ww] = fmaxf(v, 0.0f);
        }
    }
}

extern "C" void kernel_launch(void* const* d_in, const int* in_sizes, int n_in,
                              void* d_out, int out_size)
{
    const float* x  = (const float*)d_in[0];
    const float* g  = (const float*)d_in[1];
    const float* wr = (const float*)d_in[2];
    const float* s1 = (const float*)d_in[3];
    const float* b1 = (const float*)d_in[4];
    const float* s2 = (const float*)d_in[5];
    const float* b2 = (const float*)d_in[6];
    float* out = (float*)d_out;

    sga_w<0, 0><<<512, 128>>>(x, g);                 // W forward: store
    sga_w<1, 1><<<512, 128>>>(x, g);                 // W reverse: max
    sga_h<2, 1><<<512, 256>>>(x, g, s1, b1);         // H forward: max
    sga_h<3, 2><<<512, 256>>>(x, g, s1, b1);         // H reverse: max + BN1 + ReLU -> g_y
    conv_kernel<<<D_ * H_, 128>>>(wr, x, s2, b2, out);
}